// round 10
// baseline (speedup 1.0000x reference)
#include <cuda_runtime.h>
#include <cuda_bf16.h>
#include <cuda_fp16.h>
#include <mma.h>
#include <cstdint>

using namespace nvcuda;

#define NN   100000
#define EE   3200000
#define HH   64
#define KDES 768
#define RNEG 0.01f
#define BNEPS 1e-5f
#define CAP  96

typedef unsigned long long ull;

// ---------------- scratch (static __device__ globals; no allocation) ----------------
__device__ float4 g_xv[NN * 16];          // Z buffer (finalA out / finalB in)
__device__ __half2 g_xh2[NN * 32];        // node features x [N,64] in fp16 (aggregate input)
__device__ float4 g_Av[2][NN * 16];       // per-relation MEAN vectors [N,64]
__device__ int    g_cnt0[NN];             // relation-0 in-degree
__device__ int    g_ctot[NN];             // total in-degree (cursor during build)
__device__ uint32_t g_bucket[NN * CAP];   // per-dst edge payloads: src | rel<<17
__device__ float  g_bdes[HH];
__device__ float  g_Wnum[5 * HH];
__device__ float  g_bnum[HH];
__device__ float  g_Wcat[6 * HH];
__device__ float  g_bcat[HH];
__device__ float  g_Wr[2][HH * HH];       // rgcn weights, k-major (contiguous = [128][64])
// bf16-split BN-folded des weight, k-major [768][64]
__device__ unsigned short g_Bh[KDES * HH];
__device__ unsigned short g_Bl[KDES * HH];

__device__ __forceinline__ float leaky(float v) { return v > 0.f ? v : RNEG * v; }

// packed f32x2 helpers
__device__ __forceinline__ void fma2(ull& d, ull a, ull b) {
    asm("fma.rn.f32x2 %0, %1, %2, %0;" : "+l"(d) : "l"(a), "l"(b));
}
__device__ __forceinline__ ull dupf(float x) {
    ull r; asm("mov.b64 %0, {%1, %1};" : "=l"(r) : "f"(x)); return r;
}
__device__ __forceinline__ ull pk2(float a, float b) {
    ull r; asm("mov.b64 %0, {%1, %2};" : "=l"(r) : "f"(a), "f"(b)); return r;
}
__device__ __forceinline__ float2 unpk(ull v) {
    float2 r; asm("mov.b64 {%0, %1}, %2;" : "=f"(r.x), "=f"(r.y) : "l"(v)); return r;
}
__device__ __forceinline__ uint32_t bfpack(float lo, float hi) {
    uint32_t r;
    asm("cvt.rn.bf16x2.f32 %0, %1, %2;" : "=r"(r) : "f"(hi), "f"(lo));
    return r;
}
__device__ __forceinline__ uint32_t smem_u32(const void* p) {
    uint32_t a;
    asm("{ .reg .u64 t; cvta.to.shared.u64 t, %1; cvt.u32.u64 %0, t; }" : "=r"(a) : "l"(p));
    return a;
}
__device__ __forceinline__ void cp16(uint32_t dst, const void* src, int srcsize) {
    asm volatile("cp.async.cg.shared.global [%0], [%1], 16, %2;"
                 :: "r"(dst), "l"(src), "r"(srcsize) : "memory");
}
__device__ __forceinline__ void cp_commit() {
    asm volatile("cp.async.commit_group;" ::: "memory");
}
template<int N> __device__ __forceinline__ void cp_wait() {
    asm volatile("cp.async.wait_group %0;" :: "n"(N) : "memory");
}

// ---------------- prep (also zeroes per-node counters) ----------------
__global__ void prep_kernel(const float* __restrict__ desW, const float* __restrict__ desb,
                            const float* __restrict__ numW, const float* __restrict__ numb,
                            const float* __restrict__ catW, const float* __restrict__ catb,
                            const float* __restrict__ desg, const float* __restrict__ desbeta,
                            const float* __restrict__ desm, const float* __restrict__ desv,
                            const float* __restrict__ numg, const float* __restrict__ numbeta,
                            const float* __restrict__ numm, const float* __restrict__ numv,
                            const float* __restrict__ catg, const float* __restrict__ catbeta,
                            const float* __restrict__ catm, const float* __restrict__ catv,
                            const float* __restrict__ rgcnW)
{
    int idx = blockIdx.x * blockDim.x + threadIdx.x;
    if (idx < NN) { g_cnt0[idx] = 0; g_ctot[idx] = 0; }
    if (idx < KDES * HH) {
        int k = idx >> 6, n = idx & 63;
        float s = desg[n] * rsqrtf(desv[n] + BNEPS);
        float w = desW[n * KDES + k] * s;
        uint32_t hp = bfpack(w, 0.f);
        float hf = __uint_as_float(hp << 16);
        uint32_t lp = bfpack(w - hf, 0.f);
        g_Bh[k * HH + n] = (unsigned short)(hp & 0xffffu);
        g_Bl[k * HH + n] = (unsigned short)(lp & 0xffffu);
    }
    if (idx < 5 * HH) {
        int k = idx >> 6, h = idx & 63;
        float s = numg[h] * rsqrtf(numv[h] + BNEPS);
        g_Wnum[k * HH + h] = numW[h * 5 + k] * s;
    }
    if (idx < 6 * HH) {
        int k = idx >> 6, h = idx & 63;
        float s = catg[h] * rsqrtf(catv[h] + BNEPS);
        g_Wcat[k * HH + h] = catW[h * 6 + k] * s;
    }
    if (idx < 2 * HH * HH) {
        int r = idx >> 12;
        int rem = idx & 4095;
        int h = rem >> 6, k = rem & 63;
        g_Wr[r][k * HH + h] = rgcnW[r * HH * HH + h * HH + k];
    }
    if (idx < HH) {
        int h = idx;
        float sd = desg[h] * rsqrtf(desv[h] + BNEPS);
        g_bdes[h] = (desb[h] - desm[h]) * sd + desbeta[h];
        float sn = numg[h] * rsqrtf(numv[h] + BNEPS);
        g_bnum[h] = (numb[h] - numm[h]) * sn + numbeta[h];
        float sc = catg[h] * rsqrtf(catv[h] + BNEPS);
        g_bcat[h] = (catb[h] - catm[h]) * sc + catbeta[h];
    }
}

// ---------------- build: bucket edges by dst ----------------
__global__ void build_kernel(const int* __restrict__ ei, const int* __restrict__ et)
{
    int e = blockIdx.x * 256 + threadIdx.x;
    if (e >= EE) return;
    int src = ei[e];
    int dst = ei[EE + e];
    int r = et[e];
    if (r == 0) atomicAdd(&g_cnt0[dst], 1);
    int slot = atomicAdd(&g_ctot[dst], 1);
    g_bucket[dst * CAP + slot] = (uint32_t)src | ((uint32_t)r << 17);
}

// ---------------- aggregate: per-dst fp16 gather-reduce, fp32 accum, writes MEAN ----------------
// One warp per node; lane l holds feature cols {2l, 2l+1} (one half2 per gather).
__global__ __launch_bounds__(256) void aggregate_kernel()
{
    int warp = (blockIdx.x * 256 + threadIdx.x) >> 5;
    int lane = threadIdx.x & 31;
    if (warp >= NN) return;
    int node = warp;

    int tot = g_ctot[node];
    int c0 = g_cnt0[node];
    const uint32_t* bk = &g_bucket[node * CAP];
    const uint32_t* xh = (const uint32_t*)g_xh2;

    float2 a0 = make_float2(0.f, 0.f);
    float2 a1 = make_float2(0.f, 0.f);

    for (int i = 0; i < tot; i += 8) {
        int m = tot - i;
        uint32_t p[8];
        uint32_t hv[8];
#pragma unroll
        for (int j = 0; j < 8; j++) if (j < m) p[j] = bk[i + j];
#pragma unroll
        for (int j = 0; j < 8; j++) if (j < m) hv[j] = xh[(p[j] & 0x1FFFFu) * 32 + lane];
#pragma unroll
        for (int j = 0; j < 8; j++) if (j < m) {
            float2 v = __half22float2(*(__half2*)&hv[j]);
            if (p[j] >> 17) { a1.x += v.x; a1.y += v.y; }
            else            { a0.x += v.x; a0.y += v.y; }
        }
    }

    int c1 = tot - c0;
    float inv0 = 1.f / (float)max(c0, 1);
    float inv1 = 1.f / (float)max(c1, 1);
    ((float2*)&g_Av[0][node * 16])[lane] = make_float2(a0.x * inv0, a0.y * inv0);
    ((float2*)&g_Av[1][node * 16])[lane] = make_float2(a1.x * inv1, a1.y * inv1);
}

// ---------------- feat: WMMA bf16x3 GEMM, BK=32, cp.async 2-stage ring, single AH/AL/B bufs ----------------
// dynamic smem (bytes):
//   S32 @ 0      : 2 stages x [128][32] f32 = 32768
//   AH  @ 32768  : [128][40] bf16 = 10240
//   AL  @ 43008  : [128][40] bf16 = 10240
//   BH  @ 53248  : [32][72]  bf16 = 4608
//   BL  @ 57856  : [32][72]  bf16 = 4608
//   TAB @ 62464  : 896 floats = 3584     -> total 66048 => 3 CTAs/SM
//   D   @ 0      : [128][68] f32 = 34816 (overlaps S32+AH; used after last MMA)
#define ALD 40
#define BLD 72
#define DLD 68
#define F_OFF_S32 0u
#define F_OFF_AH  32768u
#define F_OFF_AL  43008u
#define F_OFF_BH  53248u
#define F_OFF_BL  57856u
#define F_OFF_TAB 62464u
#define F_SMEM_TOTAL (62464 + 3584)

__global__ __launch_bounds__(256, 3) void feat_kernel(const float* __restrict__ des,
                                                      const float* __restrict__ num,
                                                      const float* __restrict__ cat)
{
    extern __shared__ __align__(128) char sm[];
    uint32_t smb = smem_u32(sm);
    __nv_bfloat16* AH = (__nv_bfloat16*)(sm + F_OFF_AH);
    __nv_bfloat16* AL = (__nv_bfloat16*)(sm + F_OFF_AL);
    __nv_bfloat16* BH = (__nv_bfloat16*)(sm + F_OFF_BH);
    __nv_bfloat16* BL = (__nv_bfloat16*)(sm + F_OFF_BL);
    float* Df  = (float*)(sm + F_OFF_S32);
    float* tab = (float*)(sm + F_OFF_TAB);

    int tid = threadIdx.x;
    int warp = tid >> 5;
    int wr = warp >> 1;
    int wc = warp & 1;
    int row0 = blockIdx.x * 128;

    for (int i = tid; i < 896; i += 256) {
        float v;
        if (i < 64) v = g_bdes[i];
        else if (i < 128) v = g_bnum[i - 64];
        else if (i < 192) v = g_bcat[i - 128];
        else if (i < 512) v = g_Wnum[i - 192];
        else v = g_Wcat[i - 512];
        tab[i] = v;
    }

    wmma::fragment<wmma::accumulator, 16, 16, 16, float> acc[2][2];
#pragma unroll
    for (int i = 0; i < 2; i++)
#pragma unroll
        for (int j = 0; j < 2; j++) wmma::fill_fragment(acc[i][j], 0.f);

    uint2 fBh[2], fBl[2];

    auto issueA = [&](int t) {
        int kk = t * 32;
        uint32_t sbase = smb + F_OFF_S32 + (t & 1) * 16384;
#pragma unroll
        for (int i = 0; i < 4; i++) {
            int u = tid + 256 * i;
            int row = u >> 3, q = u & 7;
            int grow = row0 + row;
            int srow = min(grow, NN - 1);          // clamp addr; size=0 zero-fills OOB rows
            const float* src = &des[(size_t)srow * KDES + kk + q * 4];
            cp16(sbase + row * 128 + q * 16, src, (grow < NN) ? 16 : 0);
        }
        cp_commit();
    };
    auto gloadB = [&](int t) {
#pragma unroll
        for (int s = 0; s < 2; s++) {
            int i4 = (tid + 256 * s) * 4;
            int r = i4 >> 6, c = i4 & 63;
            fBh[s] = *(const uint2*)&g_Bh[(t * 32 + r) * HH + c];
            fBl[s] = *(const uint2*)&g_Bl[(t * 32 + r) * HH + c];
        }
    };
    auto convertA = [&](int t) {
        const char* S = sm + F_OFF_S32 + (t & 1) * 16384;
#pragma unroll
        for (int i = 0; i < 4; i++) {
            int u = tid + 256 * i;
            int row = u >> 3, q = u & 7;
            float4 f = *(const float4*)(S + row * 128 + q * 16);
            uint32_t h0 = bfpack(f.x, f.y);
            uint32_t h1 = bfpack(f.z, f.w);
            uint32_t l0 = bfpack(f.x - __uint_as_float(h0 << 16),
                                 f.y - __uint_as_float(h0 & 0xffff0000u));
            uint32_t l1 = bfpack(f.z - __uint_as_float(h1 << 16),
                                 f.w - __uint_as_float(h1 & 0xffff0000u));
            int eoff = row * ALD + q * 4;
            *(uint2*)&AH[eoff] = make_uint2(h0, h1);
            *(uint2*)&AL[eoff] = make_uint2(l0, l1);
        }
    };
    auto sstoreB = [&]() {
#pragma unroll
        for (int s = 0; s < 2; s++) {
            int i4 = (tid + 256 * s) * 4;
            int r = i4 >> 6, c = i4 & 63;
            int eoff = r * BLD + c;
            *(uint2*)&BH[eoff] = fBh[s];
            *(uint2*)&BL[eoff] = fBl[s];
        }
    };
    auto domma = [&]() {
#pragma unroll
        for (int kc = 0; kc < 2; kc++) {
#pragma unroll
            for (int j = 0; j < 2; j++) {
                wmma::fragment<wmma::matrix_b, 16, 16, 16, __nv_bfloat16, wmma::row_major> bh, bl;
                int bbase = (kc * 16) * BLD + wc * 32 + j * 16;
                wmma::load_matrix_sync(bh, BH + bbase, BLD);
                wmma::load_matrix_sync(bl, BL + bbase, BLD);
#pragma unroll
                for (int i = 0; i < 2; i++) {
                    wmma::fragment<wmma::matrix_a, 16, 16, 16, __nv_bfloat16, wmma::row_major> ah, al;
                    int abase = (wr * 32 + i * 16) * ALD + kc * 16;
                    wmma::load_matrix_sync(ah, AH + abase, ALD);
                    wmma::load_matrix_sync(al, AL + abase, ALD);
                    wmma::mma_sync(acc[i][j], ah, bh, acc[i][j]);
                    wmma::mma_sync(acc[i][j], ah, bl, acc[i][j]);
                    wmma::mma_sync(acc[i][j], al, bh, acc[i][j]);
                }
            }
        }
    };

    const int T = KDES / 32;   // 24
    issueA(0); issueA(1);
    gloadB(0);

    for (int t = 0; t < T; t++) {
        if (t + 1 < T) cp_wait<1>(); else cp_wait<0>();
        __syncthreads();                 // stage t visible; all prior domma done
        convertA(t);
        sstoreB();
        __syncthreads();                 // AH/AL/B ready; stage buffer reusable
        if (t + 2 < T) issueA(t + 2);
        if (t + 1 < T) gloadB(t + 1);
        domma();
    }
    __syncthreads();

#pragma unroll
    for (int i = 0; i < 2; i++)
#pragma unroll
        for (int j = 0; j < 2; j++)
            wmma::store_matrix_sync(Df + (wr * 32 + i * 16) * DLD + wc * 32 + j * 16,
                                    acc[i][j], DLD, wmma::mem_row_major);
    __syncthreads();

    {
        int row = tid >> 1;
        int ch = (tid & 1) * 8;
        int grow = row0 + row;
        if (grow < NN) {
            float nb[5], cb[6];
#pragma unroll
            for (int j = 0; j < 5; j++) nb[j] = num[grow * 5 + j];
#pragma unroll
            for (int j = 0; j < 6; j++) cb[j] = cat[grow * 6 + j];
            const float4* bd4 = (const float4*)tab;
            const float4* bn4 = (const float4*)(tab + 64);
            const float4* bc4 = (const float4*)(tab + 128);
#pragma unroll
            for (int cq = 0; cq < 8; cq++) {
                int cqq = ch + cq;
                float4 d = *(const float4*)&Df[row * DLD + cqq * 4];
                float4 bd = bd4[cqq];
                float4 bn = bn4[cqq];
                float4 bc = bc4[cqq];
                float vn[4] = {bn.x, bn.y, bn.z, bn.w};
                float vc[4] = {bc.x, bc.y, bc.z, bc.w};
#pragma unroll
                for (int j = 0; j < 5; j++) {
                    float4 w = ((const float4*)(tab + 192 + j * 64))[cqq];
                    vn[0] += nb[j] * w.x; vn[1] += nb[j] * w.y;
                    vn[2] += nb[j] * w.z; vn[3] += nb[j] * w.w;
                }
#pragma unroll
                for (int j = 0; j < 6; j++) {
                    float4 w = ((const float4*)(tab + 512 + j * 64))[cqq];
                    vc[0] += cb[j] * w.x; vc[1] += cb[j] * w.y;
                    vc[2] += cb[j] * w.z; vc[3] += cb[j] * w.w;
                }
                float rx = leaky(d.x + bd.x) + leaky(vn[0]) + leaky(vc[0]);
                float ry = leaky(d.y + bd.y) + leaky(vn[1]) + leaky(vc[1]);
                float rz = leaky(d.z + bd.z) + leaky(vn[2]) + leaky(vc[2]);
                float rw = leaky(d.w + bd.w) + leaky(vn[3]) + leaky(vc[3]);
                __half2 p0 = __floats2half2_rn(rx, ry);
                __half2 p1 = __floats2half2_rn(rz, rw);
                uint2 pk;
                pk.x = *(uint32_t*)&p0;
                pk.y = *(uint32_t*)&p1;
                *(uint2*)&g_xh2[grow * 32 + cqq * 2] = pk;
            }
        }
    }
}

// ---------------- finalA: Z = leaky(([M0;M1] @ [W0;W1]) * 0.5), K=128, single acc ----------------
__global__ __launch_bounds__(256) void finalA_kernel()
{
    __shared__ float As[2][16][132];
    __shared__ float Bs[2][16][64];
    int tid = threadIdx.x;
    int tx = tid & 15;
    int ty = tid >> 4;
    int row0 = blockIdx.x * 128;
    int c0 = tx * 4;
    int rl = ty * 8;

    int r0 = tid >> 2, kq0 = tid & 3;
    int r1 = (tid + 256) >> 2;
    int kb = tid >> 4, cb = (tid & 15) * 4;

    ull acc[4][4];
#pragma unroll
    for (int j = 0; j < 4; j++)
#pragma unroll
        for (int i = 0; i < 4; i++) acc[j][i] = 0ull;

    const float* Wflat = (const float*)g_Wr;

    float4 pA0, pA1, pB;
    auto gload = [&](int kk) {
        int kcat = kk + kq0 * 4;
        int rel = kcat >> 6;
        int offq = (kcat & 63) >> 2;
        int g0 = row0 + r0, g1 = row0 + r1;
        pA0 = (g0 < NN) ? g_Av[rel][g0 * 16 + offq] : make_float4(0.f, 0.f, 0.f, 0.f);
        pA1 = (g1 < NN) ? g_Av[rel][g1 * 16 + offq] : make_float4(0.f, 0.f, 0.f, 0.f);
        pB = *(const float4*)&Wflat[(kk + kb) * HH + cb];
    };
    auto sstore = [&](int buf) {
        As[buf][kq0 * 4 + 0][r0] = pA0.x;
        As[buf][kq0 * 4 + 1][r0] = pA0.y;
        As[buf][kq0 * 4 + 2][r0] = pA0.z;
        As[buf][kq0 * 4 + 3][r0] = pA0.w;
        As[buf][kq0 * 4 + 0][r1] = pA1.x;
        As[buf][kq0 * 4 + 1][r1] = pA1.y;
        As[buf][kq0 * 4 + 2][r1] = pA1.z;
        As[buf][kq0 * 4 + 3][r1] = pA1.w;
        *(float4*)&Bs[buf][kb][cb] = pB;
    };

    gload(0);
    sstore(0);
    __syncthreads();

#pragma unroll
    for (int t = 0; t < 8; t++) {
        int buf = t & 1;
        if (t + 1 < 8) gload((t + 1) * 16);
#pragma unroll
        for (int k = 0; k < 16; k++) {
            float4 b4 = *(const float4*)&Bs[buf][k][c0];
            ull bd0 = dupf(b4.x), bd1 = dupf(b4.y), bd2 = dupf(b4.z), bd3 = dupf(b4.w);
            ulonglong2 a01 = *(const ulonglong2*)&As[buf][k][rl];
            ulonglong2 a23 = *(const ulonglong2*)&As[buf][k][rl + 4];
            fma2(acc[0][0], a01.x, bd0); fma2(acc[0][1], a01.x, bd1);
            fma2(acc[0][2], a01.x, bd2); fma2(acc[0][3], a01.x, bd3);
            fma2(acc[1][0], a01.y, bd0); fma2(acc[1][1], a01.y, bd1);
            fma2(acc[1][2], a01.y, bd2); fma2(acc[1][3], a01.y, bd3);
            fma2(acc[2][0], a23.x, bd0); fma2(acc[2][1], a23.x, bd1);
            fma2(acc[2][2], a23.x, bd2); fma2(acc[2][3], a23.x, bd3);
            fma2(acc[3][0], a23.y, bd0); fma2(acc[3][1], a23.y, bd1);
            fma2(acc[3][2], a23.y, bd2); fma2(acc[3][3], a23.y, bd3);
        }
        if (t + 1 < 8) sstore((t + 1) & 1);
        __syncthreads();
    }

#pragma unroll
    for (int j = 0; j < 8; j++) {
        int grow = row0 + rl + j;
        if (grow < NN) {
            int jp = j >> 1, hi = j & 1;
            float res[4];
#pragma unroll
            for (int i = 0; i < 4; i++) {
                float2 u = unpk(acc[jp][i]);
                float v = hi ? u.y : u.x;
                res[i] = leaky(v * 0.5f);
            }
            g_xv[grow * 16 + tx] = make_float4(res[0], res[1], res[2], res[3]);
        }
    }
}

// ---------------- finalB: classifier, one thread per node ----------------
__global__ __launch_bounds__(256) void finalB_kernel(const float* __restrict__ W1,
                                                     const float* __restrict__ b1,
                                                     const float* __restrict__ W2,
                                                     const float* __restrict__ b2,
                                                     float* __restrict__ out)
{
    __shared__ ull   C1p[64][16];
    __shared__ float C2s[64];
    __shared__ float B1s[32];

    int tid = threadIdx.x;
    for (int idx = tid; idx < 1024; idx += 256) {
        int k = idx >> 4, p = idx & 15;
        C1p[k][p] = pk2(W1[(2 * p) * 64 + k], W1[(2 * p + 1) * 64 + k]);
    }
    if (tid < 64) C2s[tid] = W2[tid];
    if (tid < 32) B1s[tid] = b1[tid];
    __syncthreads();

    int n = blockIdx.x * 256 + tid;
    if (n >= NN) return;

    ull hacc[16];
#pragma unroll
    for (int p = 0; p < 16; p++) hacc[p] = 0ull;

    for (int kq = 0; kq < 16; kq++) {
        float4 z4 = g_xv[n * 16 + kq];
        float zc[4] = {z4.x, z4.y, z4.z, z4.w};
#pragma unroll
        for (int c = 0; c < 4; c++) {
            int k = kq * 4 + c;
            ull zd = dupf(zc[c]);
            const ulonglong2* wv = (const ulonglong2*)&C1p[k][0];
#pragma unroll
            for (int p2 = 0; p2 < 8; p2++) {
                ulonglong2 w = wv[p2];
                fma2(hacc[2 * p2 + 0], zd, w.x);
                fma2(hacc[2 * p2 + 1], zd, w.y);
            }
        }
    }

    float q0 = 0.f, q1 = 0.f;
#pragma unroll
    for (int p = 0; p < 16; p++) {
        float2 u = unpk(hacc[p]);
        float h0 = leaky(u.x + B1s[2 * p]);
        float h1 = leaky(u.y + B1s[2 * p + 1]);
        q0 += h0 * C2s[2 * p] + h1 * C2s[2 * p + 1];
        q1 += h0 * C2s[32 + 2 * p] + h1 * C2s[32 + 2 * p + 1];
    }
    out[n * 2 + 0] = q0 + b2[0];
    out[n * 2 + 1] = q1 + b2[1];
}

// ---------------- launch ----------------
extern "C" void kernel_launch(void* const* d_in, const int* in_sizes, int n_in,
                              void* d_out, int out_size)
{
    const float* des     = (const float*)d_in[0];
    const float* num     = (const float*)d_in[1];
    const float* cat     = (const float*)d_in[2];
    const int*   ei      = (const int*)d_in[3];
    const int*   et      = (const int*)d_in[4];
    const float* desW    = (const float*)d_in[5];
    const float* desb    = (const float*)d_in[6];
    const float* numW    = (const float*)d_in[7];
    const float* numb    = (const float*)d_in[8];
    const float* catW    = (const float*)d_in[9];
    const float* catb    = (const float*)d_in[10];
    const float* desg    = (const float*)d_in[11];
    const float* desbeta = (const float*)d_in[12];
    const float* desm    = (const float*)d_in[13];
    const float* desv    = (const float*)d_in[14];
    const float* numg    = (const float*)d_in[15];
    const float* numbeta = (const float*)d_in[16];
    const float* numm    = (const float*)d_in[17];
    const float* numv    = (const float*)d_in[18];
    const float* catg    = (const float*)d_in[19];
    const float* catbeta = (const float*)d_in[20];
    const float* catm    = (const float*)d_in[21];
    const float* catv    = (const float*)d_in[22];
    const float* rgcnW   = (const float*)d_in[23];
    const float* clsW1   = (const float*)d_in[24];
    const float* clsb1   = (const float*)d_in[25];
    const float* clsW2   = (const float*)d_in[26];
    const float* clsb2   = (const float*)d_in[27];
    float* out = (float*)d_out;

    cudaFuncSetAttribute(feat_kernel, cudaFuncAttributeMaxDynamicSharedMemorySize,
                         F_SMEM_TOTAL);

    prep_kernel<<<(2 * NN + 255) / 256, 256>>>(
        desW, desb, numW, numb, catW, catb,
        desg, desbeta, desm, desv,
        numg, numbeta, numm, numv,
        catg, catbeta, catm, catv,
        rgcnW);

    build_kernel<<<(EE + 255) / 256, 256>>>(ei, et);

    feat_kernel<<<(NN + 127) / 128, 256, F_SMEM_TOTAL>>>(des, num, cat);

    aggregate_kernel<<<(NN * 32 + 255) / 256, 256>>>();

    finalA_kernel<<<(NN + 127) / 128, 256>>>();

    finalB_kernel<<<(NN + 255) / 256, 256>>>(clsW1, clsb1, clsW2, clsb2, out);
}

// round 11
// speedup vs baseline: 1.1073x; 1.1073x over previous
#include <cuda_runtime.h>
#include <cuda_bf16.h>
#include <mma.h>
#include <cstdint>

using namespace nvcuda;

#define NN   100000
#define EE   3200000
#define HH   64
#define KDES 768
#define RNEG 0.01f
#define BNEPS 1e-5f
#define CAP  96

typedef unsigned long long ull;

// ---------------- scratch (static __device__ globals; no allocation) ----------------
__device__ float4 g_xv[(NN + 1) * 16];    // node features x [N+1,64]; row NN = zeros (dummy); reused for Z
__device__ float4 g_Av[2][NN * 16];       // per-relation MEAN vectors [N,64]
__device__ int    g_cnt0[NN];             // relation-0 in-degree
__device__ int    g_ctot[NN];             // total in-degree (cursor during build)
__device__ uint32_t g_bucket[NN * CAP];   // per-dst edge payloads: src | rel<<17
__device__ float  g_bdes[HH];
__device__ float  g_Wnum[5 * HH];
__device__ float  g_bnum[HH];
__device__ float  g_Wcat[6 * HH];
__device__ float  g_bcat[HH];
__device__ float  g_Wr[2][HH * HH];       // rgcn weights, k-major (contiguous = [128][64])
// bf16-split BN-folded des weight, k-major [768][64]
__device__ unsigned short g_Bh[KDES * HH];
__device__ unsigned short g_Bl[KDES * HH];

__device__ __forceinline__ float leaky(float v) { return v > 0.f ? v : RNEG * v; }

// packed f32x2 helpers
__device__ __forceinline__ void fma2(ull& d, ull a, ull b) {
    asm("fma.rn.f32x2 %0, %1, %2, %0;" : "+l"(d) : "l"(a), "l"(b));
}
__device__ __forceinline__ void add2(ull& d, ull a) {
    asm("add.rn.f32x2 %0, %0, %1;" : "+l"(d) : "l"(a));
}
__device__ __forceinline__ ull dupf(float x) {
    ull r; asm("mov.b64 %0, {%1, %1};" : "=l"(r) : "f"(x)); return r;
}
__device__ __forceinline__ ull pk2(float a, float b) {
    ull r; asm("mov.b64 %0, {%1, %2};" : "=l"(r) : "f"(a), "f"(b)); return r;
}
__device__ __forceinline__ float2 unpk(ull v) {
    float2 r; asm("mov.b64 {%0, %1}, %2;" : "=f"(r.x), "=f"(r.y) : "l"(v)); return r;
}
__device__ __forceinline__ uint32_t bfpack(float lo, float hi) {
    uint32_t r;
    asm("cvt.rn.bf16x2.f32 %0, %1, %2;" : "=r"(r) : "f"(hi), "f"(lo));
    return r;
}
__device__ __forceinline__ uint32_t smem_u32(const void* p) {
    uint32_t a;
    asm("{ .reg .u64 t; cvta.to.shared.u64 t, %1; cvt.u32.u64 %0, t; }" : "=r"(a) : "l"(p));
    return a;
}
__device__ __forceinline__ void cp16(uint32_t dst, const void* src, int srcsize) {
    asm volatile("cp.async.cg.shared.global [%0], [%1], 16, %2;"
                 :: "r"(dst), "l"(src), "r"(srcsize) : "memory");
}
__device__ __forceinline__ void cp_commit() {
    asm volatile("cp.async.commit_group;" ::: "memory");
}
template<int N> __device__ __forceinline__ void cp_wait() {
    asm volatile("cp.async.wait_group %0;" :: "n"(N) : "memory");
}

// ---------------- prep (also zeroes per-node counters) ----------------
__global__ void prep_kernel(const float* __restrict__ desW, const float* __restrict__ desb,
                            const float* __restrict__ numW, const float* __restrict__ numb,
                            const float* __restrict__ catW, const float* __restrict__ catb,
                            const float* __restrict__ desg, const float* __restrict__ desbeta,
                            const float* __restrict__ desm, const float* __restrict__ desv,
                            const float* __restrict__ numg, const float* __restrict__ numbeta,
                            const float* __restrict__ numm, const float* __restrict__ numv,
                            const float* __restrict__ catg, const float* __restrict__ catbeta,
                            const float* __restrict__ catm, const float* __restrict__ catv,
                            const float* __restrict__ rgcnW)
{
    int idx = blockIdx.x * blockDim.x + threadIdx.x;
    if (idx < NN) { g_cnt0[idx] = 0; g_ctot[idx] = 0; }
    if (idx < KDES * HH) {
        int k = idx >> 6, n = idx & 63;
        float s = desg[n] * rsqrtf(desv[n] + BNEPS);
        float w = desW[n * KDES + k] * s;
        uint32_t hp = bfpack(w, 0.f);
        float hf = __uint_as_float(hp << 16);
        uint32_t lp = bfpack(w - hf, 0.f);
        g_Bh[k * HH + n] = (unsigned short)(hp & 0xffffu);
        g_Bl[k * HH + n] = (unsigned short)(lp & 0xffffu);
    }
    if (idx < 5 * HH) {
        int k = idx >> 6, h = idx & 63;
        float s = numg[h] * rsqrtf(numv[h] + BNEPS);
        g_Wnum[k * HH + h] = numW[h * 5 + k] * s;
    }
    if (idx < 6 * HH) {
        int k = idx >> 6, h = idx & 63;
        float s = catg[h] * rsqrtf(catv[h] + BNEPS);
        g_Wcat[k * HH + h] = catW[h * 6 + k] * s;
    }
    if (idx < 2 * HH * HH) {
        int r = idx >> 12;
        int rem = idx & 4095;
        int h = rem >> 6, k = rem & 63;
        g_Wr[r][k * HH + h] = rgcnW[r * HH * HH + h * HH + k];
    }
    if (idx < HH) {
        int h = idx;
        float sd = desg[h] * rsqrtf(desv[h] + BNEPS);
        g_bdes[h] = (desb[h] - desm[h]) * sd + desbeta[h];
        float sn = numg[h] * rsqrtf(numv[h] + BNEPS);
        g_bnum[h] = (numb[h] - numm[h]) * sn + numbeta[h];
        float sc = catg[h] * rsqrtf(catv[h] + BNEPS);
        g_bcat[h] = (catb[h] - catm[h]) * sc + catbeta[h];
    }
}

// ---------------- build: bucket edges by dst ----------------
__global__ void build_kernel(const int* __restrict__ ei, const int* __restrict__ et)
{
    int e = blockIdx.x * 256 + threadIdx.x;
    if (e >= EE) return;
    int src = ei[e];
    int dst = ei[EE + e];
    int r = et[e];
    if (r == 0) atomicAdd(&g_cnt0[dst], 1);
    int slot = atomicAdd(&g_ctot[dst], 1);
    g_bucket[dst * CAP + slot] = (uint32_t)src | ((uint32_t)r << 17);
}

// ---------------- aggregate: per-dst gather-reduce, padded 8-wide, packed f32x2 accum ----------------
// One warp per node; lane l holds feature cols {2l, 2l+1}.
// Slots beyond tot use dummy payload NN (zero row, rel 0) -> contributes 0 to a0.
__global__ __launch_bounds__(256) void aggregate_kernel()
{
    int warp = (blockIdx.x * 256 + threadIdx.x) >> 5;
    int lane = threadIdx.x & 31;
    if (warp >= NN) return;
    int node = warp;

    int tot = g_ctot[node];
    int c0 = g_cnt0[node];
    const uint32_t* bk = &g_bucket[node * CAP];
    const ull* x2 = (const ull*)g_xv;   // float2 view, row stride 32

    ull a0 = 0ull, a1 = 0ull;
    int tpad = (tot + 7) & ~7;
    for (int i = 0; i < tpad; i += 8) {
        uint32_t p[8];
        ull v[8];
#pragma unroll
        for (int j = 0; j < 8; j++) p[j] = (i + j < tot) ? bk[i + j] : (uint32_t)NN;
#pragma unroll
        for (int j = 0; j < 8; j++) v[j] = x2[(p[j] & 0x1FFFFu) * 32 + lane];
#pragma unroll
        for (int j = 0; j < 8; j++) {
            if (p[j] >> 17) add2(a1, v[j]); else add2(a0, v[j]);
        }
    }

    int c1 = tot - c0;
    float inv0 = 1.f / (float)max(c0, 1);
    float inv1 = 1.f / (float)max(c1, 1);
    float2 r0 = unpk(a0), r1 = unpk(a1);
    ((float2*)&g_Av[0][node * 16])[lane] = make_float2(r0.x * inv0, r0.y * inv0);
    ((float2*)&g_Av[1][node * 16])[lane] = make_float2(r1.x * inv1, r1.y * inv1);
}

// ---------------- feat: WMMA bf16x3 GEMM, BK=32, cp.async 3-stage fp32 A ring (R9 version) ----------------
#define ALD 40
#define BLD 72
#define DLD 68
#define F_OFF_S32 0u
#define F_OFF_AH  49152u
#define F_OFF_AL  69632u
#define F_OFF_BH  90112u
#define F_OFF_BL  99328u
#define F_OFF_TAB 108544u
#define F_SMEM_TOTAL (108544 + 3584)

__global__ __launch_bounds__(256) void feat_kernel(const float* __restrict__ des,
                                                   const float* __restrict__ num,
                                                   const float* __restrict__ cat)
{
    extern __shared__ __align__(128) char sm[];
    uint32_t smb = smem_u32(sm);
    __nv_bfloat16* AH = (__nv_bfloat16*)(sm + F_OFF_AH);
    __nv_bfloat16* AL = (__nv_bfloat16*)(sm + F_OFF_AL);
    __nv_bfloat16* BH = (__nv_bfloat16*)(sm + F_OFF_BH);
    __nv_bfloat16* BL = (__nv_bfloat16*)(sm + F_OFF_BL);
    float* Df  = (float*)(sm + F_OFF_S32);
    float* tab = (float*)(sm + F_OFF_TAB);

    int tid = threadIdx.x;
    int warp = tid >> 5;
    int wr = warp >> 1;
    int wc = warp & 1;
    int row0 = blockIdx.x * 128;

    int arow[4], aq[4];
#pragma unroll
    for (int i = 0; i < 4; i++) {
        int u = tid + 256 * i;
        arow[i] = u >> 3;
        aq[i] = u & 7;
    }

    for (int i = tid; i < 896; i += 256) {
        float v;
        if (i < 64) v = g_bdes[i];
        else if (i < 128) v = g_bnum[i - 64];
        else if (i < 192) v = g_bcat[i - 128];
        else if (i < 512) v = g_Wnum[i - 192];
        else v = g_Wcat[i - 512];
        tab[i] = v;
    }

    wmma::fragment<wmma::accumulator, 16, 16, 16, float> acc[2][2];
#pragma unroll
    for (int i = 0; i < 2; i++)
#pragma unroll
        for (int j = 0; j < 2; j++) wmma::fill_fragment(acc[i][j], 0.f);

    uint2 fBh[2], fBl[2];

    auto issueA = [&](int t) {
        int kk = t * 32;
        uint32_t sbase = smb + F_OFF_S32 + (t % 3) * 16384;
#pragma unroll
        for (int i = 0; i < 4; i++) {
            int grow = row0 + arow[i];
            int srow = min(grow, NN - 1);
            const float* src = &des[(size_t)srow * KDES + kk + aq[i] * 4];
            cp16(sbase + arow[i] * 128 + aq[i] * 16, src, (grow < NN) ? 16 : 0);
        }
        cp_commit();
    };
    auto gloadB = [&](int t) {
#pragma unroll
        for (int s = 0; s < 2; s++) {
            int i4 = (tid + 256 * s) * 4;
            int r = i4 >> 6, c = i4 & 63;
            fBh[s] = *(const uint2*)&g_Bh[(t * 32 + r) * HH + c];
            fBl[s] = *(const uint2*)&g_Bl[(t * 32 + r) * HH + c];
        }
    };
    auto convertA = [&](int t, int b) {
        const char* S = sm + F_OFF_S32 + (t % 3) * 16384;
#pragma unroll
        for (int i = 0; i < 4; i++) {
            float4 f = *(const float4*)(S + arow[i] * 128 + aq[i] * 16);
            uint32_t h0 = bfpack(f.x, f.y);
            uint32_t h1 = bfpack(f.z, f.w);
            uint32_t l0 = bfpack(f.x - __uint_as_float(h0 << 16),
                                 f.y - __uint_as_float(h0 & 0xffff0000u));
            uint32_t l1 = bfpack(f.z - __uint_as_float(h1 << 16),
                                 f.w - __uint_as_float(h1 & 0xffff0000u));
            int eoff = (b * 128 + arow[i]) * ALD + aq[i] * 4;
            *(uint2*)&AH[eoff] = make_uint2(h0, h1);
            *(uint2*)&AL[eoff] = make_uint2(l0, l1);
        }
    };
    auto sstoreB = [&](int b) {
#pragma unroll
        for (int s = 0; s < 2; s++) {
            int i4 = (tid + 256 * s) * 4;
            int r = i4 >> 6, c = i4 & 63;
            int eoff = (b * 32 + r) * BLD + c;
            *(uint2*)&BH[eoff] = fBh[s];
            *(uint2*)&BL[eoff] = fBl[s];
        }
    };
    auto domma = [&](int b) {
#pragma unroll
        for (int kc = 0; kc < 2; kc++) {
            wmma::fragment<wmma::matrix_a, 16, 16, 16, __nv_bfloat16, wmma::row_major> ah[2], al[2];
            wmma::fragment<wmma::matrix_b, 16, 16, 16, __nv_bfloat16, wmma::row_major> bh[2], bl[2];
#pragma unroll
            for (int i = 0; i < 2; i++) {
                int base = (b * 128 + wr * 32 + i * 16) * ALD + kc * 16;
                wmma::load_matrix_sync(ah[i], AH + base, ALD);
                wmma::load_matrix_sync(al[i], AL + base, ALD);
            }
#pragma unroll
            for (int j = 0; j < 2; j++) {
                int base = (b * 32 + kc * 16) * BLD + wc * 32 + j * 16;
                wmma::load_matrix_sync(bh[j], BH + base, BLD);
                wmma::load_matrix_sync(bl[j], BL + base, BLD);
            }
#pragma unroll
            for (int i = 0; i < 2; i++)
#pragma unroll
                for (int j = 0; j < 2; j++) {
                    wmma::mma_sync(acc[i][j], ah[i], bh[j], acc[i][j]);
                    wmma::mma_sync(acc[i][j], ah[i], bl[j], acc[i][j]);
                    wmma::mma_sync(acc[i][j], al[i], bh[j], acc[i][j]);
                }
        }
    };

    const int T = KDES / 32;   // 24
    issueA(0); issueA(1); issueA(2);
    gloadB(0);

    for (int t = 0; t < T; t++) {
        int b = t & 1;
        if (t < T - 2)      cp_wait<2>();
        else if (t == T - 2) cp_wait<1>();
        else                 cp_wait<0>();
        __syncthreads();
        convertA(t, b);
        sstoreB(b);
        __syncthreads();
        if (t + 3 < T) issueA(t + 3);
        if (t + 1 < T) gloadB(t + 1);
        domma(b);
    }
    __syncthreads();

#pragma unroll
    for (int i = 0; i < 2; i++)
#pragma unroll
        for (int j = 0; j < 2; j++)
            wmma::store_matrix_sync(Df + (wr * 32 + i * 16) * DLD + wc * 32 + j * 16,
                                    acc[i][j], DLD, wmma::mem_row_major);
    __syncthreads();

    {
        int row = tid >> 1;
        int ch = (tid & 1) * 8;
        int grow = row0 + row;
        if (grow < NN) {
            float nb[5], cb[6];
#pragma unroll
            for (int j = 0; j < 5; j++) nb[j] = num[grow * 5 + j];
#pragma unroll
            for (int j = 0; j < 6; j++) cb[j] = cat[grow * 6 + j];
            const float4* bd4 = (const float4*)tab;
            const float4* bn4 = (const float4*)(tab + 64);
            const float4* bc4 = (const float4*)(tab + 128);
#pragma unroll
            for (int cq = 0; cq < 8; cq++) {
                int cqq = ch + cq;
                float4 d = *(const float4*)&Df[row * DLD + cqq * 4];
                float4 bd = bd4[cqq];
                float4 bn = bn4[cqq];
                float4 bc = bc4[cqq];
                float vn[4] = {bn.x, bn.y, bn.z, bn.w};
                float vc[4] = {bc.x, bc.y, bc.z, bc.w};
#pragma unroll
                for (int j = 0; j < 5; j++) {
                    float4 w = ((const float4*)(tab + 192 + j * 64))[cqq];
                    vn[0] += nb[j] * w.x; vn[1] += nb[j] * w.y;
                    vn[2] += nb[j] * w.z; vn[3] += nb[j] * w.w;
                }
#pragma unroll
                for (int j = 0; j < 6; j++) {
                    float4 w = ((const float4*)(tab + 512 + j * 64))[cqq];
                    vc[0] += cb[j] * w.x; vc[1] += cb[j] * w.y;
                    vc[2] += cb[j] * w.z; vc[3] += cb[j] * w.w;
                }
                float4 res;
                res.x = leaky(d.x + bd.x) + leaky(vn[0]) + leaky(vc[0]);
                res.y = leaky(d.y + bd.y) + leaky(vn[1]) + leaky(vc[1]);
                res.z = leaky(d.z + bd.z) + leaky(vn[2]) + leaky(vc[2]);
                res.w = leaky(d.w + bd.w) + leaky(vn[3]) + leaky(vc[3]);
                g_xv[grow * 16 + cqq] = res;
            }
        }
    }
}

// ---------------- finalA: Z = leaky(([M0;M1] @ [W0;W1]) * 0.5), K=128, single acc ----------------
__global__ __launch_bounds__(256) void finalA_kernel()
{
    __shared__ float As[2][16][132];
    __shared__ float Bs[2][16][64];
    int tid = threadIdx.x;
    int tx = tid & 15;
    int ty = tid >> 4;
    int row0 = blockIdx.x * 128;
    int c0 = tx * 4;
    int rl = ty * 8;

    int r0 = tid >> 2, kq0 = tid & 3;
    int r1 = (tid + 256) >> 2;
    int kb = tid >> 4, cb = (tid & 15) * 4;

    ull acc[4][4];
#pragma unroll
    for (int j = 0; j < 4; j++)
#pragma unroll
        for (int i = 0; i < 4; i++) acc[j][i] = 0ull;

    const float* Wflat = (const float*)g_Wr;

    float4 pA0, pA1, pB;
    auto gload = [&](int kk) {
        int kcat = kk + kq0 * 4;
        int rel = kcat >> 6;
        int offq = (kcat & 63) >> 2;
        int g0 = row0 + r0, g1 = row0 + r1;
        pA0 = (g0 < NN) ? g_Av[rel][g0 * 16 + offq] : make_float4(0.f, 0.f, 0.f, 0.f);
        pA1 = (g1 < NN) ? g_Av[rel][g1 * 16 + offq] : make_float4(0.f, 0.f, 0.f, 0.f);
        pB = *(const float4*)&Wflat[(kk + kb) * HH + cb];
    };
    auto sstore = [&](int buf) {
        As[buf][kq0 * 4 + 0][r0] = pA0.x;
        As[buf][kq0 * 4 + 1][r0] = pA0.y;
        As[buf][kq0 * 4 + 2][r0] = pA0.z;
        As[buf][kq0 * 4 + 3][r0] = pA0.w;
        As[buf][kq0 * 4 + 0][r1] = pA1.x;
        As[buf][kq0 * 4 + 1][r1] = pA1.y;
        As[buf][kq0 * 4 + 2][r1] = pA1.z;
        As[buf][kq0 * 4 + 3][r1] = pA1.w;
        *(float4*)&Bs[buf][kb][cb] = pB;
    };

    gload(0);
    sstore(0);
    __syncthreads();

#pragma unroll
    for (int t = 0; t < 8; t++) {
        int buf = t & 1;
        if (t + 1 < 8) gload((t + 1) * 16);
#pragma unroll
        for (int k = 0; k < 16; k++) {
            float4 b4 = *(const float4*)&Bs[buf][k][c0];
            ull bd0 = dupf(b4.x), bd1 = dupf(b4.y), bd2 = dupf(b4.z), bd3 = dupf(b4.w);
            ulonglong2 a01 = *(const ulonglong2*)&As[buf][k][rl];
            ulonglong2 a23 = *(const ulonglong2*)&As[buf][k][rl + 4];
            fma2(acc[0][0], a01.x, bd0); fma2(acc[0][1], a01.x, bd1);
            fma2(acc[0][2], a01.x, bd2); fma2(acc[0][3], a01.x, bd3);
            fma2(acc[1][0], a01.y, bd0); fma2(acc[1][1], a01.y, bd1);
            fma2(acc[1][2], a01.y, bd2); fma2(acc[1][3], a01.y, bd3);
            fma2(acc[2][0], a23.x, bd0); fma2(acc[2][1], a23.x, bd1);
            fma2(acc[2][2], a23.x, bd2); fma2(acc[2][3], a23.x, bd3);
            fma2(acc[3][0], a23.y, bd0); fma2(acc[3][1], a23.y, bd1);
            fma2(acc[3][2], a23.y, bd2); fma2(acc[3][3], a23.y, bd3);
        }
        if (t + 1 < 8) sstore((t + 1) & 1);
        __syncthreads();
    }

#pragma unroll
    for (int j = 0; j < 8; j++) {
        int grow = row0 + rl + j;
        if (grow < NN) {
            int jp = j >> 1, hi = j & 1;
            float res[4];
#pragma unroll
            for (int i = 0; i < 4; i++) {
                float2 u = unpk(acc[jp][i]);
                float v = hi ? u.y : u.x;
                res[i] = leaky(v * 0.5f);
            }
            g_xv[grow * 16 + tx] = make_float4(res[0], res[1], res[2], res[3]);
        }
    }
}

// ---------------- finalB: classifier, one thread per node ----------------
__global__ __launch_bounds__(256) void finalB_kernel(const float* __restrict__ W1,
                                                     const float* __restrict__ b1,
                                                     const float* __restrict__ W2,
                                                     const float* __restrict__ b2,
                                                     float* __restrict__ out)
{
    __shared__ ull   C1p[64][16];
    __shared__ float C2s[64];
    __shared__ float B1s[32];

    int tid = threadIdx.x;
    for (int idx = tid; idx < 1024; idx += 256) {
        int k = idx >> 4, p = idx & 15;
        C1p[k][p] = pk2(W1[(2 * p) * 64 + k], W1[(2 * p + 1) * 64 + k]);
    }
    if (tid < 64) C2s[tid] = W2[tid];
    if (tid < 32) B1s[tid] = b1[tid];
    __syncthreads();

    int n = blockIdx.x * 256 + tid;
    if (n >= NN) return;

    ull hacc[16];
#pragma unroll
    for (int p = 0; p < 16; p++) hacc[p] = 0ull;

    for (int kq = 0; kq < 16; kq++) {
        float4 z4 = g_xv[n * 16 + kq];
        float zc[4] = {z4.x, z4.y, z4.z, z4.w};
#pragma unroll
        for (int c = 0; c < 4; c++) {
            int k = kq * 4 + c;
            ull zd = dupf(zc[c]);
            const ulonglong2* wv = (const ulonglong2*)&C1p[k][0];
#pragma unroll
            for (int p2 = 0; p2 < 8; p2++) {
                ulonglong2 w = wv[p2];
                fma2(hacc[2 * p2 + 0], zd, w.x);
                fma2(hacc[2 * p2 + 1], zd, w.y);
            }
        }
    }

    float q0 = 0.f, q1 = 0.f;
#pragma unroll
    for (int p = 0; p < 16; p++) {
        float2 u = unpk(hacc[p]);
        float h0 = leaky(u.x + B1s[2 * p]);
        float h1 = leaky(u.y + B1s[2 * p + 1]);
        q0 += h0 * C2s[2 * p] + h1 * C2s[2 * p + 1];
        q1 += h0 * C2s[32 + 2 * p] + h1 * C2s[32 + 2 * p + 1];
    }
    out[n * 2 + 0] = q0 + b2[0];
    out[n * 2 + 1] = q1 + b2[1];
}

// ---------------- launch ----------------
extern "C" void kernel_launch(void* const* d_in, const int* in_sizes, int n_in,
                              void* d_out, int out_size)
{
    const float* des     = (const float*)d_in[0];
    const float* num     = (const float*)d_in[1];
    const float* cat     = (const float*)d_in[2];
    const int*   ei      = (const int*)d_in[3];
    const int*   et      = (const int*)d_in[4];
    const float* desW    = (const float*)d_in[5];
    const float* desb    = (const float*)d_in[6];
    const float* numW    = (const float*)d_in[7];
    const float* numb    = (const float*)d_in[8];
    const float* catW    = (const float*)d_in[9];
    const float* catb    = (const float*)d_in[10];
    const float* desg    = (const float*)d_in[11];
    const float* desbeta = (const float*)d_in[12];
    const float* desm    = (const float*)d_in[13];
    const float* desv    = (const float*)d_in[14];
    const float* numg    = (const float*)d_in[15];
    const float* numbeta = (const float*)d_in[16];
    const float* numm    = (const float*)d_in[17];
    const float* numv    = (const float*)d_in[18];
    const float* catg    = (const float*)d_in[19];
    const float* catbeta = (const float*)d_in[20];
    const float* catm    = (const float*)d_in[21];
    const float* catv    = (const float*)d_in[22];
    const float* rgcnW   = (const float*)d_in[23];
    const float* clsW1   = (const float*)d_in[24];
    const float* clsb1   = (const float*)d_in[25];
    const float* clsW2   = (const float*)d_in[26];
    const float* clsb2   = (const float*)d_in[27];
    float* out = (float*)d_out;

    cudaFuncSetAttribute(feat_kernel, cudaFuncAttributeMaxDynamicSharedMemorySize,
                         F_SMEM_TOTAL);

    prep_kernel<<<(2 * NN + 255) / 256, 256>>>(
        desW, desb, numW, numb, catW, catb,
        desg, desbeta, desm, desv,
        numg, numbeta, numm, numv,
        catg, catbeta, catm, catv,
        rgcnW);

    build_kernel<<<(EE + 255) / 256, 256>>>(ei, et);

    feat_kernel<<<(NN + 127) / 128, 256, F_SMEM_TOTAL>>>(des, num, cat);

    aggregate_kernel<<<(NN * 32 + 255) / 256, 256>>>();

    finalA_kernel<<<(NN + 127) / 128, 256>>>();

    finalB_kernel<<<(NN + 255) / 256, 256>>>(clsW1, clsb1, clsW2, clsb2, out);
}

// round 12
// speedup vs baseline: 1.1972x; 1.0812x over previous
#include <cuda_runtime.h>
#include <cuda_bf16.h>
#include <mma.h>
#include <cstdint>

using namespace nvcuda;

#define NN   100000
#define EE   3200000
#define HH   64
#define KDES 768
#define RNEG 0.01f
#define BNEPS 1e-5f
#define CAP  96

typedef unsigned long long ull;

// ---------------- scratch (static __device__ globals; no allocation) ----------------
__device__ float4 g_xv[(NN + 1) * 16];    // node features x [N+1,64]; row NN = zeros (dummy); reused for Z
__device__ float4 g_Av[2][NN * 16];       // per-relation MEAN vectors [N,64]
__device__ int    g_cf[NN];               // relation-0 count (front cursor)
__device__ int    g_cb[NN];               // relation-1 count (back cursor)
__device__ uint32_t g_bucket[NN * CAP];   // per-dst edge src ids; rel0 from front, rel1 from back
__device__ float  g_bdes[HH];
__device__ float  g_Wnum[5 * HH];
__device__ float  g_bnum[HH];
__device__ float  g_Wcat[6 * HH];
__device__ float  g_bcat[HH];
__device__ float  g_Wr[2][HH * HH];       // rgcn weights, k-major (contiguous = [128][64])
// bf16-split BN-folded des weight, k-major [768][64]
__device__ unsigned short g_Bh[KDES * HH];
__device__ unsigned short g_Bl[KDES * HH];

__device__ __forceinline__ float leaky(float v) { return v > 0.f ? v : RNEG * v; }

// packed f32x2 helpers
__device__ __forceinline__ void fma2(ull& d, ull a, ull b) {
    asm("fma.rn.f32x2 %0, %1, %2, %0;" : "+l"(d) : "l"(a), "l"(b));
}
__device__ __forceinline__ void add2(ull& d, ull a) {
    asm("add.rn.f32x2 %0, %0, %1;" : "+l"(d) : "l"(a));
}
__device__ __forceinline__ ull dupf(float x) {
    ull r; asm("mov.b64 %0, {%1, %1};" : "=l"(r) : "f"(x)); return r;
}
__device__ __forceinline__ ull pk2(float a, float b) {
    ull r; asm("mov.b64 %0, {%1, %2};" : "=l"(r) : "f"(a), "f"(b)); return r;
}
__device__ __forceinline__ float2 unpk(ull v) {
    float2 r; asm("mov.b64 {%0, %1}, %2;" : "=f"(r.x), "=f"(r.y) : "l"(v)); return r;
}
__device__ __forceinline__ uint32_t bfpack(float lo, float hi) {
    uint32_t r;
    asm("cvt.rn.bf16x2.f32 %0, %1, %2;" : "=r"(r) : "f"(hi), "f"(lo));
    return r;
}
__device__ __forceinline__ uint32_t smem_u32(const void* p) {
    uint32_t a;
    asm("{ .reg .u64 t; cvta.to.shared.u64 t, %1; cvt.u32.u64 %0, t; }" : "=r"(a) : "l"(p));
    return a;
}
__device__ __forceinline__ void cp16(uint32_t dst, const void* src, int srcsize) {
    asm volatile("cp.async.cg.shared.global [%0], [%1], 16, %2;"
                 :: "r"(dst), "l"(src), "r"(srcsize) : "memory");
}
__device__ __forceinline__ void cp_commit() {
    asm volatile("cp.async.commit_group;" ::: "memory");
}
template<int N> __device__ __forceinline__ void cp_wait() {
    asm volatile("cp.async.wait_group %0;" :: "n"(N) : "memory");
}

// ---------------- prep (also zeroes per-node counters) ----------------
__global__ void prep_kernel(const float* __restrict__ desW, const float* __restrict__ desb,
                            const float* __restrict__ numW, const float* __restrict__ numb,
                            const float* __restrict__ catW, const float* __restrict__ catb,
                            const float* __restrict__ desg, const float* __restrict__ desbeta,
                            const float* __restrict__ desm, const float* __restrict__ desv,
                            const float* __restrict__ numg, const float* __restrict__ numbeta,
                            const float* __restrict__ numm, const float* __restrict__ numv,
                            const float* __restrict__ catg, const float* __restrict__ catbeta,
                            const float* __restrict__ catm, const float* __restrict__ catv,
                            const float* __restrict__ rgcnW)
{
    int idx = blockIdx.x * blockDim.x + threadIdx.x;
    if (idx < NN) { g_cf[idx] = 0; g_cb[idx] = 0; }
    if (idx < KDES * HH) {
        int k = idx >> 6, n = idx & 63;
        float s = desg[n] * rsqrtf(desv[n] + BNEPS);
        float w = desW[n * KDES + k] * s;
        uint32_t hp = bfpack(w, 0.f);
        float hf = __uint_as_float(hp << 16);
        uint32_t lp = bfpack(w - hf, 0.f);
        g_Bh[k * HH + n] = (unsigned short)(hp & 0xffffu);
        g_Bl[k * HH + n] = (unsigned short)(lp & 0xffffu);
    }
    if (idx < 5 * HH) {
        int k = idx >> 6, h = idx & 63;
        float s = numg[h] * rsqrtf(numv[h] + BNEPS);
        g_Wnum[k * HH + h] = numW[h * 5 + k] * s;
    }
    if (idx < 6 * HH) {
        int k = idx >> 6, h = idx & 63;
        float s = catg[h] * rsqrtf(catv[h] + BNEPS);
        g_Wcat[k * HH + h] = catW[h * 6 + k] * s;
    }
    if (idx < 2 * HH * HH) {
        int r = idx >> 12;
        int rem = idx & 4095;
        int h = rem >> 6, k = rem & 63;
        g_Wr[r][k * HH + h] = rgcnW[r * HH * HH + h * HH + k];
    }
    if (idx < HH) {
        int h = idx;
        float sd = desg[h] * rsqrtf(desv[h] + BNEPS);
        g_bdes[h] = (desb[h] - desm[h]) * sd + desbeta[h];
        float sn = numg[h] * rsqrtf(numv[h] + BNEPS);
        g_bnum[h] = (numb[h] - numm[h]) * sn + numbeta[h];
        float sc = catg[h] * rsqrtf(catv[h] + BNEPS);
        g_bcat[h] = (catb[h] - catm[h]) * sc + catbeta[h];
    }
}

// ---------------- build: two-sided bucket by dst (rel0 front, rel1 back), 1 atomic/edge ----------------
__global__ void build_kernel(const int* __restrict__ ei, const int* __restrict__ et)
{
    int e = blockIdx.x * 256 + threadIdx.x;
    if (e >= EE) return;
    int src = ei[e];
    int dst = ei[EE + e];
    int r = et[e];
    if (r == 0) {
        int slot = atomicAdd(&g_cf[dst], 1);
        g_bucket[dst * CAP + slot] = (uint32_t)src;
    } else {
        int slot = atomicAdd(&g_cb[dst], 1);
        g_bucket[dst * CAP + (CAP - 1 - slot)] = (uint32_t)src;
    }
}

// ---------------- aggregate: two homogeneous gather loops, branchless, packed f32x2 accum ----------------
// One warp per node; lane l holds feature cols {2l, 2l+1}. Dummy slots -> zero row NN.
__global__ __launch_bounds__(256) void aggregate_kernel()
{
    int warp = (blockIdx.x * 256 + threadIdx.x) >> 5;
    int lane = threadIdx.x & 31;
    if (warp >= NN) return;
    int node = warp;

    int c0 = g_cf[node];
    int c1 = g_cb[node];
    const uint32_t* bk = &g_bucket[node * CAP];
    const ull* x2 = (const ull*)g_xv;   // float2 view, row stride 32

    ull a0 = 0ull, a1 = 0ull;

    int p0 = (c0 + 7) & ~7;
    for (int i = 0; i < p0; i += 8) {
        uint32_t p[8];
        ull v[8];
#pragma unroll
        for (int j = 0; j < 8; j++) p[j] = (i + j < c0) ? bk[i + j] : (uint32_t)NN;
#pragma unroll
        for (int j = 0; j < 8; j++) v[j] = x2[p[j] * 32 + lane];
#pragma unroll
        for (int j = 0; j < 8; j++) add2(a0, v[j]);
    }
    int p1 = (c1 + 7) & ~7;
    for (int i = 0; i < p1; i += 8) {
        uint32_t p[8];
        ull v[8];
#pragma unroll
        for (int j = 0; j < 8; j++) p[j] = (i + j < c1) ? bk[CAP - 1 - (i + j)] : (uint32_t)NN;
#pragma unroll
        for (int j = 0; j < 8; j++) v[j] = x2[p[j] * 32 + lane];
#pragma unroll
        for (int j = 0; j < 8; j++) add2(a1, v[j]);
    }

    float inv0 = 1.f / (float)max(c0, 1);
    float inv1 = 1.f / (float)max(c1, 1);
    float2 r0 = unpk(a0), r1 = unpk(a1);
    ((float2*)&g_Av[0][node * 16])[lane] = make_float2(r0.x * inv0, r0.y * inv0);
    ((float2*)&g_Av[1][node * 16])[lane] = make_float2(r1.x * inv1, r1.y * inv1);
}

// ---------------- feat: WMMA bf16x3 GEMM, BK=32, cp.async 3-stage ring, ONE barrier/iter ----------------
#define ALD 40
#define BLD 72
#define DLD 68
#define F_OFF_S32 0u
#define F_OFF_AH  49152u
#define F_OFF_AL  69632u
#define F_OFF_BH  90112u
#define F_OFF_BL  99328u
#define F_OFF_TAB 108544u
#define F_SMEM_TOTAL (108544 + 3584)

__global__ __launch_bounds__(256) void feat_kernel(const float* __restrict__ des,
                                                   const float* __restrict__ num,
                                                   const float* __restrict__ cat)
{
    extern __shared__ __align__(128) char sm[];
    uint32_t smb = smem_u32(sm);
    __nv_bfloat16* AH = (__nv_bfloat16*)(sm + F_OFF_AH);
    __nv_bfloat16* AL = (__nv_bfloat16*)(sm + F_OFF_AL);
    __nv_bfloat16* BH = (__nv_bfloat16*)(sm + F_OFF_BH);
    __nv_bfloat16* BL = (__nv_bfloat16*)(sm + F_OFF_BL);
    float* Df  = (float*)(sm + F_OFF_S32);
    float* tab = (float*)(sm + F_OFF_TAB);

    int tid = threadIdx.x;
    int warp = tid >> 5;
    int wr = warp >> 1;
    int wc = warp & 1;
    int row0 = blockIdx.x * 128;

    int arow[4], aq[4];
#pragma unroll
    for (int i = 0; i < 4; i++) {
        int u = tid + 256 * i;
        arow[i] = u >> 3;
        aq[i] = u & 7;
    }

    for (int i = tid; i < 896; i += 256) {
        float v;
        if (i < 64) v = g_bdes[i];
        else if (i < 128) v = g_bnum[i - 64];
        else if (i < 192) v = g_bcat[i - 128];
        else if (i < 512) v = g_Wnum[i - 192];
        else v = g_Wcat[i - 512];
        tab[i] = v;
    }

    wmma::fragment<wmma::accumulator, 16, 16, 16, float> acc[2][2];
#pragma unroll
    for (int i = 0; i < 2; i++)
#pragma unroll
        for (int j = 0; j < 2; j++) wmma::fill_fragment(acc[i][j], 0.f);

    uint2 fBh[2], fBl[2];

    auto issueA = [&](int t) {
        int kk = t * 32;
        uint32_t sbase = smb + F_OFF_S32 + (t % 3) * 16384;
#pragma unroll
        for (int i = 0; i < 4; i++) {
            int grow = row0 + arow[i];
            int srow = min(grow, NN - 1);
            const float* src = &des[(size_t)srow * KDES + kk + aq[i] * 4];
            cp16(sbase + arow[i] * 128 + aq[i] * 16, src, (grow < NN) ? 16 : 0);
        }
        cp_commit();
    };
    auto gloadB = [&](int t) {
#pragma unroll
        for (int s = 0; s < 2; s++) {
            int i4 = (tid + 256 * s) * 4;
            int r = i4 >> 6, c = i4 & 63;
            fBh[s] = *(const uint2*)&g_Bh[(t * 32 + r) * HH + c];
            fBl[s] = *(const uint2*)&g_Bl[(t * 32 + r) * HH + c];
        }
    };
    auto convertA = [&](int t, int b) {
        const char* S = sm + F_OFF_S32 + (t % 3) * 16384;
#pragma unroll
        for (int i = 0; i < 4; i++) {
            float4 f = *(const float4*)(S + arow[i] * 128 + aq[i] * 16);
            uint32_t h0 = bfpack(f.x, f.y);
            uint32_t h1 = bfpack(f.z, f.w);
            uint32_t l0 = bfpack(f.x - __uint_as_float(h0 << 16),
                                 f.y - __uint_as_float(h0 & 0xffff0000u));
            uint32_t l1 = bfpack(f.z - __uint_as_float(h1 << 16),
                                 f.w - __uint_as_float(h1 & 0xffff0000u));
            int eoff = (b * 128 + arow[i]) * ALD + aq[i] * 4;
            *(uint2*)&AH[eoff] = make_uint2(h0, h1);
            *(uint2*)&AL[eoff] = make_uint2(l0, l1);
        }
    };
    auto sstoreB = [&](int b) {
#pragma unroll
        for (int s = 0; s < 2; s++) {
            int i4 = (tid + 256 * s) * 4;
            int r = i4 >> 6, c = i4 & 63;
            int eoff = (b * 32 + r) * BLD + c;
            *(uint2*)&BH[eoff] = fBh[s];
            *(uint2*)&BL[eoff] = fBl[s];
        }
    };
    auto domma = [&](int b) {
#pragma unroll
        for (int kc = 0; kc < 2; kc++) {
            wmma::fragment<wmma::matrix_a, 16, 16, 16, __nv_bfloat16, wmma::row_major> ah[2], al[2];
            wmma::fragment<wmma::matrix_b, 16, 16, 16, __nv_bfloat16, wmma::row_major> bh[2], bl[2];
#pragma unroll
            for (int i = 0; i < 2; i++) {
                int base = (b * 128 + wr * 32 + i * 16) * ALD + kc * 16;
                wmma::load_matrix_sync(ah[i], AH + base, ALD);
                wmma::load_matrix_sync(al[i], AL + base, ALD);
            }
#pragma unroll
            for (int j = 0; j < 2; j++) {
                int base = (b * 32 + kc * 16) * BLD + wc * 32 + j * 16;
                wmma::load_matrix_sync(bh[j], BH + base, BLD);
                wmma::load_matrix_sync(bl[j], BL + base, BLD);
            }
#pragma unroll
            for (int i = 0; i < 2; i++)
#pragma unroll
                for (int j = 0; j < 2; j++) {
                    wmma::mma_sync(acc[i][j], ah[i], bh[j], acc[i][j]);
                    wmma::mma_sync(acc[i][j], ah[i], bl[j], acc[i][j]);
                    wmma::mma_sync(acc[i][j], al[i], bh[j], acc[i][j]);
                }
        }
    };

    const int T = KDES / 32;   // 24
    issueA(0); issueA(1); issueA(2);
    gloadB(0);

    // One barrier per iteration. Safe because:
    //  - stage ring is thread-private (each thread converts exactly the slots its own cp16 wrote)
    //  - AH/AL/BH/BL are double-buffered; convertA(t,b) vs concurrent domma(t-1,1-b) touch
    //    different buffers, and domma(t-2,b) is fenced by the barrier of iteration t-1.
    for (int t = 0; t < T; t++) {
        int b = t & 1;
        if (t < T - 2)      cp_wait<2>();
        else if (t == T - 2) cp_wait<1>();
        else                 cp_wait<0>();
        convertA(t, b);
        sstoreB(b);
        if (t + 3 < T) issueA(t + 3);
        if (t + 1 < T) gloadB(t + 1);
        __syncthreads();
        domma(b);
    }
    __syncthreads();

#pragma unroll
    for (int i = 0; i < 2; i++)
#pragma unroll
        for (int j = 0; j < 2; j++)
            wmma::store_matrix_sync(Df + (wr * 32 + i * 16) * DLD + wc * 32 + j * 16,
                                    acc[i][j], DLD, wmma::mem_row_major);
    __syncthreads();

    {
        int row = tid >> 1;
        int ch = (tid & 1) * 8;
        int grow = row0 + row;
        if (grow < NN) {
            float nb[5], cb[6];
#pragma unroll
            for (int j = 0; j < 5; j++) nb[j] = num[grow * 5 + j];
#pragma unroll
            for (int j = 0; j < 6; j++) cb[j] = cat[grow * 6 + j];
            const float4* bd4 = (const float4*)tab;
            const float4* bn4 = (const float4*)(tab + 64);
            const float4* bc4 = (const float4*)(tab + 128);
#pragma unroll
            for (int cq = 0; cq < 8; cq++) {
                int cqq = ch + cq;
                float4 d = *(const float4*)&Df[row * DLD + cqq * 4];
                float4 bd = bd4[cqq];
                float4 bn = bn4[cqq];
                float4 bc = bc4[cqq];
                float vn[4] = {bn.x, bn.y, bn.z, bn.w};
                float vc[4] = {bc.x, bc.y, bc.z, bc.w};
#pragma unroll
                for (int j = 0; j < 5; j++) {
                    float4 w = ((const float4*)(tab + 192 + j * 64))[cqq];
                    vn[0] += nb[j] * w.x; vn[1] += nb[j] * w.y;
                    vn[2] += nb[j] * w.z; vn[3] += nb[j] * w.w;
                }
#pragma unroll
                for (int j = 0; j < 6; j++) {
                    float4 w = ((const float4*)(tab + 512 + j * 64))[cqq];
                    vc[0] += cb[j] * w.x; vc[1] += cb[j] * w.y;
                    vc[2] += cb[j] * w.z; vc[3] += cb[j] * w.w;
                }
                float4 res;
                res.x = leaky(d.x + bd.x) + leaky(vn[0]) + leaky(vc[0]);
                res.y = leaky(d.y + bd.y) + leaky(vn[1]) + leaky(vc[1]);
                res.z = leaky(d.z + bd.z) + leaky(vn[2]) + leaky(vc[2]);
                res.w = leaky(d.w + bd.w) + leaky(vn[3]) + leaky(vc[3]);
                g_xv[grow * 16 + cqq] = res;
            }
        }
    }
}

// ---------------- finalA: Z = leaky(([M0;M1] @ [W0;W1]) * 0.5), K=128, single acc ----------------
__global__ __launch_bounds__(256) void finalA_kernel()
{
    __shared__ float As[2][16][132];
    __shared__ float Bs[2][16][64];
    int tid = threadIdx.x;
    int tx = tid & 15;
    int ty = tid >> 4;
    int row0 = blockIdx.x * 128;
    int c0 = tx * 4;
    int rl = ty * 8;

    int r0 = tid >> 2, kq0 = tid & 3;
    int r1 = (tid + 256) >> 2;
    int kb = tid >> 4, cb = (tid & 15) * 4;

    ull acc[4][4];
#pragma unroll
    for (int j = 0; j < 4; j++)
#pragma unroll
        for (int i = 0; i < 4; i++) acc[j][i] = 0ull;

    const float* Wflat = (const float*)g_Wr;

    float4 pA0, pA1, pB;
    auto gload = [&](int kk) {
        int kcat = kk + kq0 * 4;
        int rel = kcat >> 6;
        int offq = (kcat & 63) >> 2;
        int g0 = row0 + r0, g1 = row0 + r1;
        pA0 = (g0 < NN) ? g_Av[rel][g0 * 16 + offq] : make_float4(0.f, 0.f, 0.f, 0.f);
        pA1 = (g1 < NN) ? g_Av[rel][g1 * 16 + offq] : make_float4(0.f, 0.f, 0.f, 0.f);
        pB = *(const float4*)&Wflat[(kk + kb) * HH + cb];
    };
    auto sstore = [&](int buf) {
        As[buf][kq0 * 4 + 0][r0] = pA0.x;
        As[buf][kq0 * 4 + 1][r0] = pA0.y;
        As[buf][kq0 * 4 + 2][r0] = pA0.z;
        As[buf][kq0 * 4 + 3][r0] = pA0.w;
        As[buf][kq0 * 4 + 0][r1] = pA1.x;
        As[buf][kq0 * 4 + 1][r1] = pA1.y;
        As[buf][kq0 * 4 + 2][r1] = pA1.z;
        As[buf][kq0 * 4 + 3][r1] = pA1.w;
        *(float4*)&Bs[buf][kb][cb] = pB;
    };

    gload(0);
    sstore(0);
    __syncthreads();

#pragma unroll
    for (int t = 0; t < 8; t++) {
        int buf = t & 1;
        if (t + 1 < 8) gload((t + 1) * 16);
#pragma unroll
        for (int k = 0; k < 16; k++) {
            float4 b4 = *(const float4*)&Bs[buf][k][c0];
            ull bd0 = dupf(b4.x), bd1 = dupf(b4.y), bd2 = dupf(b4.z), bd3 = dupf(b4.w);
            ulonglong2 a01 = *(const ulonglong2*)&As[buf][k][rl];
            ulonglong2 a23 = *(const ulonglong2*)&As[buf][k][rl + 4];
            fma2(acc[0][0], a01.x, bd0); fma2(acc[0][1], a01.x, bd1);
            fma2(acc[0][2], a01.x, bd2); fma2(acc[0][3], a01.x, bd3);
            fma2(acc[1][0], a01.y, bd0); fma2(acc[1][1], a01.y, bd1);
            fma2(acc[1][2], a01.y, bd2); fma2(acc[1][3], a01.y, bd3);
            fma2(acc[2][0], a23.x, bd0); fma2(acc[2][1], a23.x, bd1);
            fma2(acc[2][2], a23.x, bd2); fma2(acc[2][3], a23.x, bd3);
            fma2(acc[3][0], a23.y, bd0); fma2(acc[3][1], a23.y, bd1);
            fma2(acc[3][2], a23.y, bd2); fma2(acc[3][3], a23.y, bd3);
        }
        if (t + 1 < 8) sstore((t + 1) & 1);
        __syncthreads();
    }

#pragma unroll
    for (int j = 0; j < 8; j++) {
        int grow = row0 + rl + j;
        if (grow < NN) {
            int jp = j >> 1, hi = j & 1;
            float res[4];
#pragma unroll
            for (int i = 0; i < 4; i++) {
                float2 u = unpk(acc[jp][i]);
                float v = hi ? u.y : u.x;
                res[i] = leaky(v * 0.5f);
            }
            g_xv[grow * 16 + tx] = make_float4(res[0], res[1], res[2], res[3]);
        }
    }
}

// ---------------- finalB: classifier, one thread per node ----------------
__global__ __launch_bounds__(256) void finalB_kernel(const float* __restrict__ W1,
                                                     const float* __restrict__ b1,
                                                     const float* __restrict__ W2,
                                                     const float* __restrict__ b2,
                                                     float* __restrict__ out)
{
    __shared__ ull   C1p[64][16];
    __shared__ float C2s[64];
    __shared__ float B1s[32];

    int tid = threadIdx.x;
    for (int idx = tid; idx < 1024; idx += 256) {
        int k = idx >> 4, p = idx & 15;
        C1p[k][p] = pk2(W1[(2 * p) * 64 + k], W1[(2 * p + 1) * 64 + k]);
    }
    if (tid < 64) C2s[tid] = W2[tid];
    if (tid < 32) B1s[tid] = b1[tid];
    __syncthreads();

    int n = blockIdx.x * 256 + tid;
    if (n >= NN) return;

    ull hacc[16];
#pragma unroll
    for (int p = 0; p < 16; p++) hacc[p] = 0ull;

    for (int kq = 0; kq < 16; kq++) {
        float4 z4 = g_xv[n * 16 + kq];
        float zc[4] = {z4.x, z4.y, z4.z, z4.w};
#pragma unroll
        for (int c = 0; c < 4; c++) {
            int k = kq * 4 + c;
            ull zd = dupf(zc[c]);
            const ulonglong2* wv = (const ulonglong2*)&C1p[k][0];
#pragma unroll
            for (int p2 = 0; p2 < 8; p2++) {
                ulonglong2 w = wv[p2];
                fma2(hacc[2 * p2 + 0], zd, w.x);
                fma2(hacc[2 * p2 + 1], zd, w.y);
            }
        }
    }

    float q0 = 0.f, q1 = 0.f;
#pragma unroll
    for (int p = 0; p < 16; p++) {
        float2 u = unpk(hacc[p]);
        float h0 = leaky(u.x + B1s[2 * p]);
        float h1 = leaky(u.y + B1s[2 * p + 1]);
        q0 += h0 * C2s[2 * p] + h1 * C2s[2 * p + 1];
        q1 += h0 * C2s[32 + 2 * p] + h1 * C2s[32 + 2 * p + 1];
    }
    out[n * 2 + 0] = q0 + b2[0];
    out[n * 2 + 1] = q1 + b2[1];
}

// ---------------- launch ----------------
extern "C" void kernel_launch(void* const* d_in, const int* in_sizes, int n_in,
                              void* d_out, int out_size)
{
    const float* des     = (const float*)d_in[0];
    const float* num     = (const float*)d_in[1];
    const float* cat     = (const float*)d_in[2];
    const int*   ei      = (const int*)d_in[3];
    const int*   et      = (const int*)d_in[4];
    const float* desW    = (const float*)d_in[5];
    const float* desb    = (const float*)d_in[6];
    const float* numW    = (const float*)d_in[7];
    const float* numb    = (const float*)d_in[8];
    const float* catW    = (const float*)d_in[9];
    const float* catb    = (const float*)d_in[10];
    const float* desg    = (const float*)d_in[11];
    const float* desbeta = (const float*)d_in[12];
    const float* desm    = (const float*)d_in[13];
    const float* desv    = (const float*)d_in[14];
    const float* numg    = (const float*)d_in[15];
    const float* numbeta = (const float*)d_in[16];
    const float* numm    = (const float*)d_in[17];
    const float* numv    = (const float*)d_in[18];
    const float* catg    = (const float*)d_in[19];
    const float* catbeta = (const float*)d_in[20];
    const float* catm    = (const float*)d_in[21];
    const float* catv    = (const float*)d_in[22];
    const float* rgcnW   = (const float*)d_in[23];
    const float* clsW1   = (const float*)d_in[24];
    const float* clsb1   = (const float*)d_in[25];
    const float* clsW2   = (const float*)d_in[26];
    const float* clsb2   = (const float*)d_in[27];
    float* out = (float*)d_out;

    cudaFuncSetAttribute(feat_kernel, cudaFuncAttributeMaxDynamicSharedMemorySize,
                         F_SMEM_TOTAL);

    prep_kernel<<<(2 * NN + 255) / 256, 256>>>(
        desW, desb, numW, numb, catW, catb,
        desg, desbeta, desm, desv,
        numg, numbeta, numm, numv,
        catg, catbeta, catm, catv,
        rgcnW);

    build_kernel<<<(EE + 255) / 256, 256>>>(ei, et);

    feat_kernel<<<(NN + 127) / 128, 256, F_SMEM_TOTAL>>>(des, num, cat);

    aggregate_kernel<<<(NN * 32 + 255) / 256, 256>>>();

    finalA_kernel<<<(NN + 127) / 128, 256>>>();

    finalB_kernel<<<(NN + 255) / 256, 256>>>(clsW1, clsb1, clsW2, clsb2, out);
}